// round 16
// baseline (speedup 1.0000x reference)
#include <cuda_runtime.h>
#include <cuda_fp16.h>
#include <math.h>
#include <stdint.h>

// ---------------- problem constants ----------------
#define BATCH 4
#define SEQ   2048
#define CEMB  1024
#define NHEAD 16
#define HDIM  64
#define ROWS  (BATCH*SEQ)        // 8192
#define C3    (3*CEMB)           // 3072
#define C4    (4*CEMB)           // 4096

// softmax scale folded with log2(e): S is produced directly in exp2 domain
#define QK_SCALE_LOG2 0.1803368801111204f   // 0.125 * log2(e)

// ---------------- scratch (no cudaMalloc allowed) ----------------
__device__ float  g_x2 [(size_t)ROWS*CEMB];
__device__ __half g_qkv[(size_t)ROWS*C3];
__device__ __half g_a  [(size_t)ROWS*CEMB];
__device__ __half g_y  [(size_t)ROWS*CEMB];
__device__ __half g_h  [(size_t)ROWS*C4];
__device__ __half g_wq [(size_t)C3*CEMB];
__device__ __half g_wp [(size_t)CEMB*CEMB];
__device__ __half g_wf [(size_t)C4*CEMB];
__device__ __half g_w2 [(size_t)CEMB*C4];

// ---------------- PTX helpers (family-safe: cp.async / ldmatrix / mma.sync) ----------------
__device__ __forceinline__ uint32_t s2u(const void* p) {
    uint32_t a;
    asm("{ .reg .u64 t; cvta.to.shared.u64 t, %1; cvt.u32.u64 %0, t; }" : "=r"(a) : "l"(p));
    return a;
}
__device__ __forceinline__ uint32_t swz(uint32_t o) { return o ^ ((o >> 3) & 0x70); }

__device__ __forceinline__ void cp16(uint32_t s, const void* g) {
    asm volatile("cp.async.cg.shared.global [%0], [%1], 16;" :: "r"(s), "l"(g));
}
__device__ __forceinline__ void cp_commit() { asm volatile("cp.async.commit_group;"); }
#define CP_WAIT(N) asm volatile("cp.async.wait_group %0;" :: "n"(N))

__device__ __forceinline__ void ldsm4(uint32_t* r, uint32_t addr) {
    asm volatile("ldmatrix.sync.aligned.m8n8.x4.shared.b16 {%0,%1,%2,%3}, [%4];"
                 : "=r"(r[0]), "=r"(r[1]), "=r"(r[2]), "=r"(r[3]) : "r"(addr));
}
__device__ __forceinline__ void ldsm4t(uint32_t* r, uint32_t addr) {
    asm volatile("ldmatrix.sync.aligned.m8n8.x4.trans.shared.b16 {%0,%1,%2,%3}, [%4];"
                 : "=r"(r[0]), "=r"(r[1]), "=r"(r[2]), "=r"(r[3]) : "r"(addr));
}
// fp16 inputs, fp32 accumulate
__device__ __forceinline__ void mma16816(float* c, const uint32_t* a, const uint32_t* b) {
    asm volatile("mma.sync.aligned.m16n8k16.row.col.f32.f16.f16.f32 "
                 "{%0,%1,%2,%3}, {%4,%5,%6,%7}, {%8,%9}, {%0,%1,%2,%3};"
                 : "+f"(c[0]), "+f"(c[1]), "+f"(c[2]), "+f"(c[3])
                 : "r"(a[0]), "r"(a[1]), "r"(a[2]), "r"(a[3]), "r"(b[0]), "r"(b[1]));
}
__device__ __forceinline__ float ex2f(float x) {
    float r;
    asm("ex2.approx.ftz.f32 %0, %1;" : "=f"(r) : "f"(x));
    return r;
}

__device__ __forceinline__ uint32_t packh2(float x, float y) {
    __half2 h = __floats2half2_rn(x, y);
    return *reinterpret_cast<uint32_t*>(&h);
}
__device__ __forceinline__ void store_h2(__half* p, size_t off, float v0, float v1) {
    __half2 h = __floats2half2_rn(v0, v1);
    *reinterpret_cast<__half2*>(p + off) = h;
}

// ---------------- layernorm -> fp16 : warp per row, shuffle-only ----------------
// 256 threads = 8 warps = 8 rows per block; grid = ROWS/8
__global__ void ln_h_kernel(const float* __restrict__ x, const float* __restrict__ g,
                            const float* __restrict__ b, __half* __restrict__ oh) {
    const int wid = threadIdx.x >> 5, lane = threadIdx.x & 31;
    const int row = blockIdx.x * 8 + wid;
    const float* xr = x + (size_t)row * CEMB;

    float4 v[8];
    float s = 0.f, sq = 0.f;
    #pragma unroll
    for (int i = 0; i < 8; ++i) {
        v[i] = *(const float4*)(xr + lane * 4 + i * 128);
        s  += v[i].x + v[i].y + v[i].z + v[i].w;
        sq += v[i].x * v[i].x + v[i].y * v[i].y + v[i].z * v[i].z + v[i].w * v[i].w;
    }
    #pragma unroll
    for (int o = 16; o; o >>= 1) {
        s  += __shfl_xor_sync(0xffffffffu, s,  o);
        sq += __shfl_xor_sync(0xffffffffu, sq, o);
    }
    const float mu   = s * (1.f / CEMB);
    const float var  = sq * (1.f / CEMB) - mu * mu;
    const float rstd = rsqrtf(var + 1e-5f);

    __half* orow = oh + (size_t)row * CEMB;
    #pragma unroll
    for (int i = 0; i < 8; ++i) {
        const float4 gg = *(const float4*)(g + lane * 4 + i * 128);
        const float4 bb = *(const float4*)(b + lane * 4 + i * 128);
        __half2 h0 = __floats2half2_rn((v[i].x - mu) * rstd * gg.x + bb.x,
                                       (v[i].y - mu) * rstd * gg.y + bb.y);
        __half2 h1 = __floats2half2_rn((v[i].z - mu) * rstd * gg.z + bb.z,
                                       (v[i].w - mu) * rstd * gg.w + bb.w);
        uint2 pk;
        pk.x = *reinterpret_cast<uint32_t*>(&h0);
        pk.y = *reinterpret_cast<uint32_t*>(&h1);
        *reinterpret_cast<uint2*>(orow + lane * 4 + i * 128) = pk;
    }
}

// ---------------- merged weight transpose: all 4 weights, one launch ----------------
__global__ void wt_all_kernel(const float* __restrict__ w_attn, __half* __restrict__ wq,
                              const float* __restrict__ w_proj, __half* __restrict__ wp,
                              const float* __restrict__ w_fc,   __half* __restrict__ wf,
                              const float* __restrict__ w_fc2,  __half* __restrict__ w2) {
    int id = blockIdx.x;
    const float* w; __half* wh; int K, N, nt, kt;
    if (id < 3072)      { w = w_attn; wh = wq; K = CEMB; N = C3;   nt = id % 96;  kt = id / 96;  }
    else if (id < 4096) { id -= 3072; w = w_proj; wh = wp; K = CEMB; N = CEMB; nt = id % 32;  kt = id / 32;  }
    else if (id < 8192) { id -= 4096; w = w_fc;   wh = wf; K = CEMB; N = C4;   nt = id % 128; kt = id / 128; }
    else                { id -= 8192; w = w_fc2;  wh = w2; K = C4;   N = CEMB; nt = id % 32;  kt = id / 32;  }
    const int n0 = nt * 32, k0 = kt * 32;

    __shared__ float t[32][33];
    int tx = threadIdx.x, ty = threadIdx.y;
    #pragma unroll
    for (int i = 0; i < 4; ++i)
        t[ty + 8 * i][tx] = w[(size_t)(k0 + ty + 8 * i) * N + n0 + tx];
    __syncthreads();
    #pragma unroll
    for (int i = 0; i < 4; ++i) {
        int r = ty + 8 * i;
        wh[(size_t)(n0 + r) * K + k0 + tx] = __float2half(t[tx][r]);
    }
}

__device__ __forceinline__ float gelu_t(float v) {
    float u = 0.7978845608028654f * (v + 0.044715f * v * v * v);
    return 0.5f * v * (1.f + tanhf(u));
}

// ---------------- HMMA GEMM 256x128, 8 warps (4m x 2n), warp tile 64x64 ----------------
// EPI: 1=bias+gelu->h, 2=bias+res->f32, 3=bias->h with q-columns (col<CEMB) pre-scaled
#define TILE_M 256
#define TILE_N 128
#define KCH    64
#define STAGES 4
#define STG_BYTES (TILE_M * 128 + TILE_N * 128)   // 49152
#define GSMEM (STAGES * STG_BYTES)                // 196608

template<int EPI>
__global__ __launch_bounds__(256, 1) void hmma_gemm(
    const __half* __restrict__ A, const __half* __restrict__ B,
    const float* __restrict__ bias, const float* __restrict__ res,
    float* __restrict__ Cf, __half* __restrict__ Ch,
    int M, int N, int K)
{
    extern __shared__ char smem[];
    const uint32_t sb = s2u(smem);
    const int tid = threadIdx.x, wid = tid >> 5, lane = tid & 31;
    const int wm = wid & 3, wn = wid >> 2;                 // 4 x 2 warp grid
    const int row0 = blockIdx.y * TILE_M, col0 = blockIdx.x * TILE_N;
    const int NKC = K / KCH;

    auto load_chunk = [&](int kc) {
        int s = kc % STAGES;
        int k0 = kc * KCH;
        uint32_t sA = sb + s * STG_BYTES;
        uint32_t sB = sA + TILE_M * 128;
        #pragma unroll
        for (int i = 0; i < 8; ++i) {
            int idx = i * 256 + tid;
            int r = idx >> 3, c = (idx & 7) * 16;
            cp16(sA + swz(r * 128 + c), A + (size_t)(row0 + r) * K + k0 + (c >> 1));
        }
        #pragma unroll
        for (int i = 0; i < 4; ++i) {
            int idx = i * 256 + tid;
            int r = idx >> 3, c = (idx & 7) * 16;
            cp16(sB + swz(r * 128 + c), B + (size_t)(col0 + r) * K + k0 + (c >> 1));
        }
        cp_commit();
    };

    float acc[4][8][4];
    #pragma unroll
    for (int mt = 0; mt < 4; ++mt)
        #pragma unroll
        for (int nt = 0; nt < 8; ++nt)
            #pragma unroll
            for (int q = 0; q < 4; ++q) acc[mt][nt][q] = 0.f;

    for (int kc = 0; kc < STAGES - 1; ++kc) load_chunk(kc);

    const int arow = (lane & 7) + ((lane >> 3) & 1) * 8;
    const int akof = ((lane >> 4) & 1) * 8;
    const int nsel = (lane >> 4) & 1;
    const int bro  = lane & 7;
    const int bk8  = ((lane >> 3) & 1) * 8;

    for (int kc = 0; kc < NKC; ++kc) {
        int s = kc % STAGES;
        CP_WAIT(STAGES - 2);
        __syncthreads();
        if (kc + STAGES - 1 < NKC) load_chunk(kc + STAGES - 1);
        else cp_commit();
        uint32_t sA = sb + s * STG_BYTES;
        uint32_t sB = sA + TILE_M * 128;
        #pragma unroll
        for (int ks = 0; ks < KCH / 16; ++ks) {
            uint32_t a[4][4], b[8][2];
            #pragma unroll
            for (int mt = 0; mt < 4; ++mt) {
                uint32_t o = (uint32_t)(wm * 64 + mt * 16 + arow) * 128 + (ks * 16 + akof) * 2;
                ldsm4(a[mt], sA + swz(o));
            }
            #pragma unroll
            for (int ntp = 0; ntp < 4; ++ntp) {
                uint32_t o = (uint32_t)(wn * 64 + (2 * ntp + nsel) * 8 + bro) * 128 +
                             (ks * 16 + bk8) * 2;
                uint32_t r4[4];
                ldsm4(r4, sB + swz(o));
                b[2 * ntp][0] = r4[0]; b[2 * ntp][1] = r4[1];
                b[2 * ntp + 1][0] = r4[2]; b[2 * ntp + 1][1] = r4[3];
            }
            #pragma unroll
            for (int mt = 0; mt < 4; ++mt)
                #pragma unroll
                for (int nt = 0; nt < 8; ++nt)
                    mma16816(acc[mt][nt], a[mt], b[nt]);
        }
    }

    const int g = lane >> 2, i2 = (lane & 3) * 2;
    #pragma unroll
    for (int mt = 0; mt < 4; ++mt) {
        #pragma unroll
        for (int nt = 0; nt < 8; ++nt) {
            int r = row0 + wm * 64 + mt * 16 + g;
            int c = col0 + wn * 64 + nt * 8 + i2;
            float2 bv = *(const float2*)(bias + c);
            #pragma unroll
            for (int half = 0; half < 2; ++half) {
                int rr = r + half * 8;
                float v0 = acc[mt][nt][half * 2 + 0] + bv.x;
                float v1 = acc[mt][nt][half * 2 + 1] + bv.y;
                if (EPI == 1) {
                    store_h2(Ch, (size_t)rr * N + c, gelu_t(v0), gelu_t(v1));
                } else if (EPI == 3) {
                    // q columns carry the softmax scale in log2 domain
                    if (c < CEMB) { v0 *= QK_SCALE_LOG2; v1 *= QK_SCALE_LOG2; }
                    store_h2(Ch, (size_t)rr * N + c, v0, v1);
                } else {
                    float2 rv = *(const float2*)(res + (size_t)rr * N + c);
                    float2 ov; ov.x = v0 + rv.x; ov.y = v1 + rv.y;
                    *(float2*)(Cf + (size_t)rr * N + c) = ov;
                }
            }
        }
    }
}

// ---------------- HMMA flash attention (fp16, exp2-domain softmax) ----------------
// Q tile 128 (8 warps x 16 rows), K tile 64. smem: Q 16KB + 2 stages x 16KB = 48KB.
// Heavy tiles (large qb) issued FIRST. Q is pre-scaled by 0.125*log2(e) at qkv epilogue.
#define AQT 128
#define AKT 64
#define ASMEM (16384 + 2 * 16384)   // 49152

__global__ __launch_bounds__(256, 2) void attn_hmma(
    const __half* __restrict__ qkv, __half* __restrict__ y)
{
    extern __shared__ char smem[];
    const uint32_t sb = s2u(smem);
    const int tid = threadIdx.x, wid = tid >> 5, lane = tid & 31;
    const int qb = gridDim.x - 1 - blockIdx.x;          // heavy-first ordering
    const int bh = blockIdx.y;
    const int b = bh >> 4, h = bh & 15;
    const int q0 = qb * AQT;
    const size_t rowbase = (size_t)b * SEQ;
    const size_t qcol = (size_t)h * HDIM, kcol = CEMB + qcol, vcol = 2 * CEMB + qcol;

    const uint32_t sQ = sb;

    // G0: Q tile (16KB)
    #pragma unroll
    for (int i = 0; i < 4; ++i) {
        int idx = i * 256 + tid;
        int r = idx >> 3, c = (idx & 7) * 16;
        cp16(sQ + swz(r * 128 + c), qkv + (rowbase + q0 + r) * C3 + qcol + (c >> 1));
    }
    cp_commit();

    auto load_kv = [&](int kt, int s) {
        uint32_t base = sb + 16384 + s * 16384;
        #pragma unroll
        for (int i = 0; i < 2; ++i) {
            int idx = i * 256 + tid;
            int r = idx >> 3, c = (idx & 7) * 16;
            size_t grow = (rowbase + kt * AKT + r) * C3;
            uint32_t so = swz(r * 128 + c);
            cp16(base + so,        qkv + grow + kcol + (c >> 1));
            cp16(base + 8192 + so, qkv + grow + vcol + (c >> 1));
        }
        cp_commit();
    };

    const int nkt = 2 * qb + 2;
    load_kv(0, 0);
    load_kv(1, 1);

    float m0 = -1e30f, m1 = -1e30f, l0 = 0.f, l1 = 0.f;
    float o_[8][4];
    #pragma unroll
    for (int nt = 0; nt < 8; ++nt)
        #pragma unroll
        for (int q = 0; q < 4; ++q) o_[nt][q] = 0.f;

    const int g = lane >> 2;
    const int qr0 = q0 + wid * 16 + g;
    const int ccol = (lane & 3) * 2;
    const int frow = (lane & 7) + ((lane >> 3) & 1) * 8;
    const int fkof = ((lane >> 4) & 1) * 8;
    const int nsel = (lane >> 4) & 1;
    const int bro  = lane & 7;
    const int bk8  = ((lane >> 3) & 1) * 8;
    const int vrow = lane & 15;
    const int vsel = (lane >> 4) & 1;

    for (int kt = 0; kt < nkt; ++kt) {
        int s = kt & 1;
        CP_WAIT(1);
        __syncthreads();
        uint32_t K_ = sb + 16384 + s * 16384;
        uint32_t V_ = K_ + 8192;

        // S = Q K^T  (already in exp2 domain — Q pre-scaled)
        float sa[8][4];
        #pragma unroll
        for (int nt = 0; nt < 8; ++nt)
            sa[nt][0] = sa[nt][1] = sa[nt][2] = sa[nt][3] = 0.f;
        #pragma unroll
        for (int ks = 0; ks < 4; ++ks) {
            uint32_t qo = (uint32_t)(wid * 16 + frow) * 128 + (ks * 16 + fkof) * 2;
            uint32_t q4[4];
            ldsm4(q4, sQ + swz(qo));
            #pragma unroll
            for (int ntp = 0; ntp < 4; ++ntp) {
                uint32_t ko = (uint32_t)((2 * ntp + nsel) * 8 + bro) * 128 + (ks * 16 + bk8) * 2;
                uint32_t k4[4];
                ldsm4(k4, K_ + swz(ko));
                mma16816(sa[2 * ntp],     q4, k4);
                mma16816(sa[2 * ntp + 1], q4, k4 + 2);
            }
        }

        // causal mask (diagonal tiles only)
        const int k0g = kt * AKT;
        if ((k0g + AKT - 1) > qr0) {
            #pragma unroll
            for (int nt = 0; nt < 8; ++nt) {
                int c0g = k0g + nt * 8 + ccol;
                if (c0g > qr0)         sa[nt][0] = -1e30f;
                if (c0g + 1 > qr0)     sa[nt][1] = -1e30f;
                if (c0g > qr0 + 8)     sa[nt][2] = -1e30f;
                if (c0g + 1 > qr0 + 8) sa[nt][3] = -1e30f;
            }
        }

        // online softmax in exp2 domain
        float mt0 = -1e30f, mt1 = -1e30f;
        #pragma unroll
        for (int nt = 0; nt < 8; ++nt) {
            mt0 = fmaxf(mt0, fmaxf(sa[nt][0], sa[nt][1]));
            mt1 = fmaxf(mt1, fmaxf(sa[nt][2], sa[nt][3]));
        }
        mt0 = fmaxf(mt0, __shfl_xor_sync(0xffffffffu, mt0, 1));
        mt0 = fmaxf(mt0, __shfl_xor_sync(0xffffffffu, mt0, 2));
        mt1 = fmaxf(mt1, __shfl_xor_sync(0xffffffffu, mt1, 1));
        mt1 = fmaxf(mt1, __shfl_xor_sync(0xffffffffu, mt1, 2));
        float mn0 = fmaxf(m0, mt0), mn1 = fmaxf(m1, mt1);
        float a0 = ex2f(m0 - mn0), a1 = ex2f(m1 - mn1);
        m0 = mn0; m1 = mn1;
        float rs0 = 0.f, rs1 = 0.f;
        #pragma unroll
        for (int nt = 0; nt < 8; ++nt) {
            sa[nt][0] = ex2f(sa[nt][0] - mn0);
            sa[nt][1] = ex2f(sa[nt][1] - mn0);
            sa[nt][2] = ex2f(sa[nt][2] - mn1);
            sa[nt][3] = ex2f(sa[nt][3] - mn1);
            rs0 += sa[nt][0] + sa[nt][1];
            rs1 += sa[nt][2] + sa[nt][3];
        }
        rs0 += __shfl_xor_sync(0xffffffffu, rs0, 1);
        rs0 += __shfl_xor_sync(0xffffffffu, rs0, 2);
        rs1 += __shfl_xor_sync(0xffffffffu, rs1, 1);
        rs1 += __shfl_xor_sync(0xffffffffu, rs1, 2);
        l0 = l0 * a0 + rs0;
        l1 = l1 * a1 + rs1;
        #pragma unroll
        for (int nt = 0; nt < 8; ++nt) {
            o_[nt][0] *= a0; o_[nt][1] *= a0;
            o_[nt][2] *= a1; o_[nt][3] *= a1;
        }

        // pack P to fp16 A-fragments in registers
        uint32_t ph[4][4];
        #pragma unroll
        for (int ks = 0; ks < 4; ++ks) {
            ph[ks][0] = packh2(sa[2 * ks][0],     sa[2 * ks][1]);
            ph[ks][1] = packh2(sa[2 * ks][2],     sa[2 * ks][3]);
            ph[ks][2] = packh2(sa[2 * ks + 1][0], sa[2 * ks + 1][1]);
            ph[ks][3] = packh2(sa[2 * ks + 1][2], sa[2 * ks + 1][3]);
        }

        // O += P V, V via paired ldmatrix.x4.trans
        #pragma unroll
        for (int ks = 0; ks < 4; ++ks) {
            #pragma unroll
            for (int ntp = 0; ntp < 4; ++ntp) {
                uint32_t vo = (uint32_t)(ks * 16 + vrow) * 128 + (2 * ntp + vsel) * 16;
                uint32_t v4[4];
                ldsm4t(v4, V_ + swz(vo));
                mma16816(o_[2 * ntp],     ph[ks], v4);
                mma16816(o_[2 * ntp + 1], ph[ks], v4 + 2);
            }
        }
        __syncthreads();
        if (kt + 2 < nkt) load_kv(kt + 2, s);
        else cp_commit();
    }

    // epilogue: y = O / l -> fp16
    float i0 = 1.f / l0, i1 = 1.f / l1;
    #pragma unroll
    for (int nt = 0; nt < 8; ++nt) {
        size_t col = qcol + nt * 8 + ccol;
        store_h2(y, (rowbase + qr0) * CEMB + col,     o_[nt][0] * i0, o_[nt][1] * i0);
        store_h2(y, (rowbase + qr0 + 8) * CEMB + col, o_[nt][2] * i1, o_[nt][3] * i1);
    }
}

// ---------------- launch ----------------
extern "C" void kernel_launch(void* const* d_in, const int* in_sizes, int n_in,
                              void* d_out, int out_size) {
    const float* x      = (const float*)d_in[0];
    const float* ln1_g  = (const float*)d_in[1];
    const float* ln1_b  = (const float*)d_in[2];
    const float* w_attn = (const float*)d_in[3];
    const float* b_attn = (const float*)d_in[4];
    const float* w_proj = (const float*)d_in[5];
    const float* b_proj = (const float*)d_in[6];
    const float* ln2_g  = (const float*)d_in[7];
    const float* ln2_b  = (const float*)d_in[8];
    const float* w_fc   = (const float*)d_in[9];
    const float* b_fc   = (const float*)d_in[10];
    const float* w_fc2  = (const float*)d_in[11];
    const float* b_fc2  = (const float*)d_in[12];
    float* out = (float*)d_out;

    void* p;
    cudaGetSymbolAddress(&p, g_x2);  float* x2  = (float*)p;
    cudaGetSymbolAddress(&p, g_qkv); __half* qv = (__half*)p;
    cudaGetSymbolAddress(&p, g_a);   __half* ah = (__half*)p;
    cudaGetSymbolAddress(&p, g_y);   __half* yh = (__half*)p;
    cudaGetSymbolAddress(&p, g_h);   __half* hh = (__half*)p;
    cudaGetSymbolAddress(&p, g_wq);  __half* wq = (__half*)p;
    cudaGetSymbolAddress(&p, g_wp);  __half* wp = (__half*)p;
    cudaGetSymbolAddress(&p, g_wf);  __half* wf = (__half*)p;
    cudaGetSymbolAddress(&p, g_w2);  __half* w2 = (__half*)p;

    cudaFuncSetAttribute(hmma_gemm<1>, cudaFuncAttributeMaxDynamicSharedMemorySize, GSMEM);
    cudaFuncSetAttribute(hmma_gemm<2>, cudaFuncAttributeMaxDynamicSharedMemorySize, GSMEM);
    cudaFuncSetAttribute(hmma_gemm<3>, cudaFuncAttributeMaxDynamicSharedMemorySize, GSMEM);
    cudaFuncSetAttribute(attn_hmma, cudaFuncAttributeMaxDynamicSharedMemorySize, ASMEM);

    // all 4 weight transposes in ONE launch (12288 tiles)
    wt_all_kernel<<<12288, dim3(32, 8)>>>(w_attn, wq, w_proj, wp, w_fc, wf, w_fc2, w2);

    // 1) ln1(x) -> fp16 (warp per row)
    ln_h_kernel<<<ROWS / 8, 256>>>(x, ln1_g, ln1_b, ah);
    // 2) qkv = ln1 @ w_attn + b_attn -> fp16 (q-part pre-scaled into exp2 domain)
    hmma_gemm<3><<<dim3(C3 / TILE_N, ROWS / TILE_M), 256, GSMEM>>>(
        ah, wq, b_attn, nullptr, nullptr, qv, ROWS, C3, CEMB);
    // 3) attention -> fp16 y (heavy q-tiles first)
    attn_hmma<<<dim3(SEQ / AQT, BATCH * NHEAD), 256, ASMEM>>>(qv, yh);
    // 4) x2 = x + y @ w_proj + b_proj (f32)
    hmma_gemm<2><<<dim3(CEMB / TILE_N, ROWS / TILE_M), 256, GSMEM>>>(
        yh, wp, b_proj, x, x2, nullptr, ROWS, CEMB, CEMB);
    // 5) ln2(x2) -> fp16 (warp per row)
    ln_h_kernel<<<ROWS / 8, 256>>>(x2, ln2_g, ln2_b, ah);
    // 6) h = gelu(ln2 @ w_fc + b_fc) -> fp16
    hmma_gemm<1><<<dim3(C4 / TILE_N, ROWS / TILE_M), 256, GSMEM>>>(
        ah, wf, b_fc, nullptr, nullptr, hh, ROWS, C4, CEMB);
    // 7) out = x2 + h @ w_fc2 + b_fc2 (f32)
    hmma_gemm<2><<<dim3(CEMB / TILE_N, ROWS / TILE_M), 256, GSMEM>>>(
        hh, w2, b_fc2, x2, out, nullptr, ROWS, CEMB, C4);
}

// round 17
// speedup vs baseline: 1.5275x; 1.5275x over previous
#include <cuda_runtime.h>
#include <cuda_fp16.h>
#include <math.h>
#include <stdint.h>

// ---------------- problem constants ----------------
#define BATCH 4
#define SEQ   2048
#define CEMB  1024
#define NHEAD 16
#define HDIM  64
#define ROWS  (BATCH*SEQ)        // 8192
#define C3    (3*CEMB)           // 3072
#define C4    (4*CEMB)           // 4096

// softmax scale folded with log2(e): S arrives in exp2 domain
#define QK_SCALE_LOG2 0.1803368801111204f   // 0.125 * log2(e)

// ---------------- scratch (no cudaMalloc allowed) ----------------
__device__ float  g_x2 [(size_t)ROWS*CEMB];
__device__ __half g_qkv[(size_t)ROWS*C3];
__device__ __half g_a  [(size_t)ROWS*CEMB];
__device__ __half g_y  [(size_t)ROWS*CEMB];
__device__ __half g_h  [(size_t)ROWS*C4];
__device__ __half g_wq [(size_t)C3*CEMB];
__device__ __half g_wp [(size_t)CEMB*CEMB];
__device__ __half g_wf [(size_t)C4*CEMB];
__device__ __half g_w2 [(size_t)CEMB*C4];

// ---------------- PTX helpers (family-safe: cp.async / ldmatrix / mma.sync) ----------------
__device__ __forceinline__ uint32_t s2u(const void* p) {
    uint32_t a;
    asm("{ .reg .u64 t; cvta.to.shared.u64 t, %1; cvt.u32.u64 %0, t; }" : "=r"(a) : "l"(p));
    return a;
}
__device__ __forceinline__ uint32_t swz(uint32_t o) { return o ^ ((o >> 3) & 0x70); }

__device__ __forceinline__ void cp16(uint32_t s, const void* g) {
    asm volatile("cp.async.cg.shared.global [%0], [%1], 16;" :: "r"(s), "l"(g));
}
__device__ __forceinline__ void cp_commit() { asm volatile("cp.async.commit_group;"); }
#define CP_WAIT(N) asm volatile("cp.async.wait_group %0;" :: "n"(N))

__device__ __forceinline__ void ldsm4(uint32_t* r, uint32_t addr) {
    asm volatile("ldmatrix.sync.aligned.m8n8.x4.shared.b16 {%0,%1,%2,%3}, [%4];"
                 : "=r"(r[0]), "=r"(r[1]), "=r"(r[2]), "=r"(r[3]) : "r"(addr));
}
__device__ __forceinline__ void ldsm4t(uint32_t* r, uint32_t addr) {
    asm volatile("ldmatrix.sync.aligned.m8n8.x4.trans.shared.b16 {%0,%1,%2,%3}, [%4];"
                 : "=r"(r[0]), "=r"(r[1]), "=r"(r[2]), "=r"(r[3]) : "r"(addr));
}
// fp16 inputs, fp32 accumulate
__device__ __forceinline__ void mma16816(float* c, const uint32_t* a, const uint32_t* b) {
    asm volatile("mma.sync.aligned.m16n8k16.row.col.f32.f16.f16.f32 "
                 "{%0,%1,%2,%3}, {%4,%5,%6,%7}, {%8,%9}, {%0,%1,%2,%3};"
                 : "+f"(c[0]), "+f"(c[1]), "+f"(c[2]), "+f"(c[3])
                 : "r"(a[0]), "r"(a[1]), "r"(a[2]), "r"(a[3]), "r"(b[0]), "r"(b[1]));
}
__device__ __forceinline__ float ex2f(float x) {
    float r;
    asm("ex2.approx.ftz.f32 %0, %1;" : "=f"(r) : "f"(x));
    return r;
}

__device__ __forceinline__ uint32_t packh2(float x, float y) {
    __half2 h = __floats2half2_rn(x, y);
    return *reinterpret_cast<uint32_t*>(&h);
}
__device__ __forceinline__ void store_h2(__half* p, size_t off, float v0, float v1) {
    __half2 h = __floats2half2_rn(v0, v1);
    *reinterpret_cast<__half2*>(p + off) = h;
}

// ---------------- layernorm -> fp16 (block per row — the PROVEN R15 version) ----------------
__global__ void ln_h_kernel(const float* __restrict__ x, const float* __restrict__ g,
                            const float* __restrict__ b, __half* __restrict__ oh) {
    int row = blockIdx.x;
    int tid = threadIdx.x;
    const float4 v = ((const float4*)(x + (size_t)row * CEMB))[tid];
    float s  = v.x + v.y + v.z + v.w;
    float sq = v.x * v.x + v.y * v.y + v.z * v.z + v.w * v.w;
    #pragma unroll
    for (int o = 16; o; o >>= 1) {
        s  += __shfl_xor_sync(0xffffffffu, s,  o);
        sq += __shfl_xor_sync(0xffffffffu, sq, o);
    }
    __shared__ float ss[8], sqs[8];
    if ((tid & 31) == 0) { ss[tid >> 5] = s; sqs[tid >> 5] = sq; }
    __syncthreads();
    float tot = 0.f, totq = 0.f;
    #pragma unroll
    for (int w = 0; w < 8; ++w) { tot += ss[w]; totq += sqs[w]; }
    const float mu   = tot * (1.f / CEMB);
    const float var  = totq * (1.f / CEMB) - mu * mu;
    const float rstd = rsqrtf(var + 1e-5f);
    const float4 gg = ((const float4*)g)[tid];
    const float4 bb = ((const float4*)b)[tid];
    size_t off = (size_t)row * CEMB + tid * 4;
    store_h2(oh, off,     (v.x - mu) * rstd * gg.x + bb.x, (v.y - mu) * rstd * gg.y + bb.y);
    store_h2(oh, off + 2, (v.z - mu) * rstd * gg.z + bb.z, (v.w - mu) * rstd * gg.w + bb.w);
}

// ---------------- merged weight transpose: all 4 weights, one launch ----------------
__global__ void wt_all_kernel(const float* __restrict__ w_attn, __half* __restrict__ wq,
                              const float* __restrict__ w_proj, __half* __restrict__ wp,
                              const float* __restrict__ w_fc,   __half* __restrict__ wf,
                              const float* __restrict__ w_fc2,  __half* __restrict__ w2) {
    int id = blockIdx.x;
    const float* w; __half* wh; int K, N, nt, kt;
    if (id < 3072)      { w = w_attn; wh = wq; K = CEMB; N = C3;   nt = id % 96;  kt = id / 96;  }
    else if (id < 4096) { id -= 3072; w = w_proj; wh = wp; K = CEMB; N = CEMB; nt = id % 32;  kt = id / 32;  }
    else if (id < 8192) { id -= 4096; w = w_fc;   wh = wf; K = CEMB; N = C4;   nt = id % 128; kt = id / 128; }
    else                { id -= 8192; w = w_fc2;  wh = w2; K = C4;   N = CEMB; nt = id % 32;  kt = id / 32;  }
    const int n0 = nt * 32, k0 = kt * 32;

    __shared__ float t[32][33];
    int tx = threadIdx.x, ty = threadIdx.y;
    #pragma unroll
    for (int i = 0; i < 4; ++i)
        t[ty + 8 * i][tx] = w[(size_t)(k0 + ty + 8 * i) * N + n0 + tx];
    __syncthreads();
    #pragma unroll
    for (int i = 0; i < 4; ++i) {
        int r = ty + 8 * i;
        wh[(size_t)(n0 + r) * K + k0 + tx] = __float2half(t[tx][r]);
    }
}

__device__ __forceinline__ float gelu_t(float v) {
    float u = 0.7978845608028654f * (v + 0.044715f * v * v * v);
    return 0.5f * v * (1.f + tanhf(u));
}

// ---------------- HMMA GEMM 256x128, 8 warps (4m x 2n), warp tile 64x64 ----------------
// EPI: 1=bias+gelu->h, 2=bias+res->f32, 3=bias->h with q-columns (col<CEMB) pre-scaled
#define TILE_M 256
#define TILE_N 128
#define KCH    64
#define STAGES 4
#define STG_BYTES (TILE_M * 128 + TILE_N * 128)   // 49152
#define GSMEM (STAGES * STG_BYTES)                // 196608

template<int EPI>
__global__ __launch_bounds__(256, 1) void hmma_gemm(
    const __half* __restrict__ A, const __half* __restrict__ B,
    const float* __restrict__ bias, const float* __restrict__ res,
    float* __restrict__ Cf, __half* __restrict__ Ch,
    int M, int N, int K)
{
    extern __shared__ char smem[];
    const uint32_t sb = s2u(smem);
    const int tid = threadIdx.x, wid = tid >> 5, lane = tid & 31;
    const int wm = wid & 3, wn = wid >> 2;                 // 4 x 2 warp grid
    const int row0 = blockIdx.y * TILE_M, col0 = blockIdx.x * TILE_N;
    const int NKC = K / KCH;

    auto load_chunk = [&](int kc) {
        int s = kc % STAGES;
        int k0 = kc * KCH;
        uint32_t sA = sb + s * STG_BYTES;
        uint32_t sB = sA + TILE_M * 128;
        #pragma unroll
        for (int i = 0; i < 8; ++i) {
            int idx = i * 256 + tid;
            int r = idx >> 3, c = (idx & 7) * 16;
            cp16(sA + swz(r * 128 + c), A + (size_t)(row0 + r) * K + k0 + (c >> 1));
        }
        #pragma unroll
        for (int i = 0; i < 4; ++i) {
            int idx = i * 256 + tid;
            int r = idx >> 3, c = (idx & 7) * 16;
            cp16(sB + swz(r * 128 + c), B + (size_t)(col0 + r) * K + k0 + (c >> 1));
        }
        cp_commit();
    };

    float acc[4][8][4];
    #pragma unroll
    for (int mt = 0; mt < 4; ++mt)
        #pragma unroll
        for (int nt = 0; nt < 8; ++nt)
            #pragma unroll
            for (int q = 0; q < 4; ++q) acc[mt][nt][q] = 0.f;

    for (int kc = 0; kc < STAGES - 1; ++kc) load_chunk(kc);

    const int arow = (lane & 7) + ((lane >> 3) & 1) * 8;
    const int akof = ((lane >> 4) & 1) * 8;
    const int nsel = (lane >> 4) & 1;
    const int bro  = lane & 7;
    const int bk8  = ((lane >> 3) & 1) * 8;

    for (int kc = 0; kc < NKC; ++kc) {
        int s = kc % STAGES;
        CP_WAIT(STAGES - 2);
        __syncthreads();
        if (kc + STAGES - 1 < NKC) load_chunk(kc + STAGES - 1);
        else cp_commit();
        uint32_t sA = sb + s * STG_BYTES;
        uint32_t sB = sA + TILE_M * 128;
        #pragma unroll
        for (int ks = 0; ks < KCH / 16; ++ks) {
            uint32_t a[4][4], b[8][2];
            #pragma unroll
            for (int mt = 0; mt < 4; ++mt) {
                uint32_t o = (uint32_t)(wm * 64 + mt * 16 + arow) * 128 + (ks * 16 + akof) * 2;
                ldsm4(a[mt], sA + swz(o));
            }
            #pragma unroll
            for (int ntp = 0; ntp < 4; ++ntp) {
                uint32_t o = (uint32_t)(wn * 64 + (2 * ntp + nsel) * 8 + bro) * 128 +
                             (ks * 16 + bk8) * 2;
                uint32_t r4[4];
                ldsm4(r4, sB + swz(o));
                b[2 * ntp][0] = r4[0]; b[2 * ntp][1] = r4[1];
                b[2 * ntp + 1][0] = r4[2]; b[2 * ntp + 1][1] = r4[3];
            }
            #pragma unroll
            for (int mt = 0; mt < 4; ++mt)
                #pragma unroll
                for (int nt = 0; nt < 8; ++nt)
                    mma16816(acc[mt][nt], a[mt], b[nt]);
        }
    }

    const int g = lane >> 2, i2 = (lane & 3) * 2;
    #pragma unroll
    for (int mt = 0; mt < 4; ++mt) {
        #pragma unroll
        for (int nt = 0; nt < 8; ++nt) {
            int r = row0 + wm * 64 + mt * 16 + g;
            int c = col0 + wn * 64 + nt * 8 + i2;
            float2 bv = *(const float2*)(bias + c);
            #pragma unroll
            for (int half = 0; half < 2; ++half) {
                int rr = r + half * 8;
                float v0 = acc[mt][nt][half * 2 + 0] + bv.x;
                float v1 = acc[mt][nt][half * 2 + 1] + bv.y;
                if (EPI == 1) {
                    store_h2(Ch, (size_t)rr * N + c, gelu_t(v0), gelu_t(v1));
                } else if (EPI == 3) {
                    // q columns carry the softmax scale in log2 domain
                    if (c < CEMB) { v0 *= QK_SCALE_LOG2; v1 *= QK_SCALE_LOG2; }
                    store_h2(Ch, (size_t)rr * N + c, v0, v1);
                } else {
                    float2 rv = *(const float2*)(res + (size_t)rr * N + c);
                    float2 ov; ov.x = v0 + rv.x; ov.y = v1 + rv.y;
                    *(float2*)(Cf + (size_t)rr * N + c) = ov;
                }
            }
        }
    }
}

// ---------------- HMMA flash attention (fp16, exp2-domain softmax) ----------------
// Q tile 128 (8 warps x 16 rows), K tile 64. smem: Q 16KB + 2 stages x 16KB = 48KB.
// Heavy tiles (large qb) first. Q pre-scaled by 0.125*log2(e) at the qkv epilogue.
#define AQT 128
#define AKT 64
#define ASMEM (16384 + 2 * 16384)   // 49152

__global__ __launch_bounds__(256, 2) void attn_hmma(
    const __half* __restrict__ qkv, __half* __restrict__ y)
{
    extern __shared__ char smem[];
    const uint32_t sb = s2u(smem);
    const int tid = threadIdx.x, wid = tid >> 5, lane = tid & 31;
    const int qb = gridDim.x - 1 - blockIdx.x;          // heavy-first ordering
    const int bh = blockIdx.y;
    const int b = bh >> 4, h = bh & 15;
    const int q0 = qb * AQT;
    const size_t rowbase = (size_t)b * SEQ;
    const size_t qcol = (size_t)h * HDIM, kcol = CEMB + qcol, vcol = 2 * CEMB + qcol;

    const uint32_t sQ = sb;

    // G0: Q tile (16KB)
    #pragma unroll
    for (int i = 0; i < 4; ++i) {
        int idx = i * 256 + tid;
        int r = idx >> 3, c = (idx & 7) * 16;
        cp16(sQ + swz(r * 128 + c), qkv + (rowbase + q0 + r) * C3 + qcol + (c >> 1));
    }
    cp_commit();

    auto load_kv = [&](int kt, int s) {
        uint32_t base = sb + 16384 + s * 16384;
        #pragma unroll
        for (int i = 0; i < 2; ++i) {
            int idx = i * 256 + tid;
            int r = idx >> 3, c = (idx & 7) * 16;
            size_t grow = (rowbase + kt * AKT + r) * C3;
            uint32_t so = swz(r * 128 + c);
            cp16(base + so,        qkv + grow + kcol + (c >> 1));
            cp16(base + 8192 + so, qkv + grow + vcol + (c >> 1));
        }
        cp_commit();
    };

    const int nkt = 2 * qb + 2;
    load_kv(0, 0);
    load_kv(1, 1);

    float m0 = -1e30f, m1 = -1e30f, l0 = 0.f, l1 = 0.f;
    float o_[8][4];
    #pragma unroll
    for (int nt = 0; nt < 8; ++nt)
        #pragma unroll
        for (int q = 0; q < 4; ++q) o_[nt][q] = 0.f;

    const int g = lane >> 2;
    const int qr0 = q0 + wid * 16 + g;
    const int ccol = (lane & 3) * 2;
    const int frow = (lane & 7) + ((lane >> 3) & 1) * 8;
    const int fkof = ((lane >> 4) & 1) * 8;
    const int nsel = (lane >> 4) & 1;
    const int bro  = lane & 7;
    const int bk8  = ((lane >> 3) & 1) * 8;
    const int vrow = lane & 15;
    const int vsel = (lane >> 4) & 1;

    for (int kt = 0; kt < nkt; ++kt) {
        int s = kt & 1;
        CP_WAIT(1);
        __syncthreads();
        uint32_t K_ = sb + 16384 + s * 16384;
        uint32_t V_ = K_ + 8192;

        // S = Q K^T (already in exp2 domain — Q pre-scaled)
        float sa[8][4];
        #pragma unroll
        for (int nt = 0; nt < 8; ++nt)
            sa[nt][0] = sa[nt][1] = sa[nt][2] = sa[nt][3] = 0.f;
        #pragma unroll
        for (int ks = 0; ks < 4; ++ks) {
            uint32_t qo = (uint32_t)(wid * 16 + frow) * 128 + (ks * 16 + fkof) * 2;
            uint32_t q4[4];
            ldsm4(q4, sQ + swz(qo));
            #pragma unroll
            for (int ntp = 0; ntp < 4; ++ntp) {
                uint32_t ko = (uint32_t)((2 * ntp + nsel) * 8 + bro) * 128 + (ks * 16 + bk8) * 2;
                uint32_t k4[4];
                ldsm4(k4, K_ + swz(ko));
                mma16816(sa[2 * ntp],     q4, k4);
                mma16816(sa[2 * ntp + 1], q4, k4 + 2);
            }
        }

        // causal mask (R15 structure)
        const int k0g = kt * AKT;
        const bool tmask = (k0g + AKT - 1) > qr0;
        if (tmask) {
            #pragma unroll
            for (int nt = 0; nt < 8; ++nt) {
                int c0g = k0g + nt * 8 + ccol;
                if (c0g > qr0)         sa[nt][0] = -1e30f;
                if (c0g + 1 > qr0)     sa[nt][1] = -1e30f;
                if (c0g > qr0 + 8)     sa[nt][2] = -1e30f;
                if (c0g + 1 > qr0 + 8) sa[nt][3] = -1e30f;
            }
        }

        // online softmax (exp2 domain)
        float mt0 = -1e30f, mt1 = -1e30f;
        #pragma unroll
        for (int nt = 0; nt < 8; ++nt) {
            mt0 = fmaxf(mt0, fmaxf(sa[nt][0], sa[nt][1]));
            mt1 = fmaxf(mt1, fmaxf(sa[nt][2], sa[nt][3]));
        }
        mt0 = fmaxf(mt0, __shfl_xor_sync(0xffffffffu, mt0, 1));
        mt0 = fmaxf(mt0, __shfl_xor_sync(0xffffffffu, mt0, 2));
        mt1 = fmaxf(mt1, __shfl_xor_sync(0xffffffffu, mt1, 1));
        mt1 = fmaxf(mt1, __shfl_xor_sync(0xffffffffu, mt1, 2));
        float mn0 = fmaxf(m0, mt0), mn1 = fmaxf(m1, mt1);
        float a0 = ex2f(m0 - mn0), a1 = ex2f(m1 - mn1);
        m0 = mn0; m1 = mn1;
        float rs0 = 0.f, rs1 = 0.f;
        #pragma unroll
        for (int nt = 0; nt < 8; ++nt) {
            sa[nt][0] = ex2f(sa[nt][0] - mn0);
            sa[nt][1] = ex2f(sa[nt][1] - mn0);
            sa[nt][2] = ex2f(sa[nt][2] - mn1);
            sa[nt][3] = ex2f(sa[nt][3] - mn1);
            rs0 += sa[nt][0] + sa[nt][1];
            rs1 += sa[nt][2] + sa[nt][3];
        }
        rs0 += __shfl_xor_sync(0xffffffffu, rs0, 1);
        rs0 += __shfl_xor_sync(0xffffffffu, rs0, 2);
        rs1 += __shfl_xor_sync(0xffffffffu, rs1, 1);
        rs1 += __shfl_xor_sync(0xffffffffu, rs1, 2);
        l0 = l0 * a0 + rs0;
        l1 = l1 * a1 + rs1;
        #pragma unroll
        for (int nt = 0; nt < 8; ++nt) {
            o_[nt][0] *= a0; o_[nt][1] *= a0;
            o_[nt][2] *= a1; o_[nt][3] *= a1;
        }

        // pack P to fp16 A-fragments in registers
        uint32_t ph[4][4];
        #pragma unroll
        for (int ks = 0; ks < 4; ++ks) {
            ph[ks][0] = packh2(sa[2 * ks][0],     sa[2 * ks][1]);
            ph[ks][1] = packh2(sa[2 * ks][2],     sa[2 * ks][3]);
            ph[ks][2] = packh2(sa[2 * ks + 1][0], sa[2 * ks + 1][1]);
            ph[ks][3] = packh2(sa[2 * ks + 1][2], sa[2 * ks + 1][3]);
        }

        // O += P V, V via paired ldmatrix.x4.trans
        #pragma unroll
        for (int ks = 0; ks < 4; ++ks) {
            #pragma unroll
            for (int ntp = 0; ntp < 4; ++ntp) {
                uint32_t vo = (uint32_t)(ks * 16 + vrow) * 128 + (2 * ntp + vsel) * 16;
                uint32_t v4[4];
                ldsm4t(v4, V_ + swz(vo));
                mma16816(o_[2 * ntp],     ph[ks], v4);
                mma16816(o_[2 * ntp + 1], ph[ks], v4 + 2);
            }
        }
        __syncthreads();
        if (kt + 2 < nkt) load_kv(kt + 2, s);
        else cp_commit();
    }

    // epilogue: y = O / l -> fp16
    float i0 = 1.f / l0, i1 = 1.f / l1;
    #pragma unroll
    for (int nt = 0; nt < 8; ++nt) {
        size_t col = qcol + nt * 8 + ccol;
        store_h2(y, (rowbase + qr0) * CEMB + col,     o_[nt][0] * i0, o_[nt][1] * i0);
        store_h2(y, (rowbase + qr0 + 8) * CEMB + col, o_[nt][2] * i1, o_[nt][3] * i1);
    }
}

// ---------------- launch ----------------
extern "C" void kernel_launch(void* const* d_in, const int* in_sizes, int n_in,
                              void* d_out, int out_size) {
    const float* x      = (const float*)d_in[0];
    const float* ln1_g  = (const float*)d_in[1];
    const float* ln1_b  = (const float*)d_in[2];
    const float* w_attn = (const float*)d_in[3];
    const float* b_attn = (const float*)d_in[4];
    const float* w_proj = (const float*)d_in[5];
    const float* b_proj = (const float*)d_in[6];
    const float* ln2_g  = (const float*)d_in[7];
    const float* ln2_b  = (const float*)d_in[8];
    const float* w_fc   = (const float*)d_in[9];
    const float* b_fc   = (const float*)d_in[10];
    const float* w_fc2  = (const float*)d_in[11];
    const float* b_fc2  = (const float*)d_in[12];
    float* out = (float*)d_out;

    void* p;
    cudaGetSymbolAddress(&p, g_x2);  float* x2  = (float*)p;
    cudaGetSymbolAddress(&p, g_qkv); __half* qv = (__half*)p;
    cudaGetSymbolAddress(&p, g_a);   __half* ah = (__half*)p;
    cudaGetSymbolAddress(&p, g_y);   __half* yh = (__half*)p;
    cudaGetSymbolAddress(&p, g_h);   __half* hh = (__half*)p;
    cudaGetSymbolAddress(&p, g_wq);  __half* wq = (__half*)p;
    cudaGetSymbolAddress(&p, g_wp);  __half* wp = (__half*)p;
    cudaGetSymbolAddress(&p, g_wf);  __half* wf = (__half*)p;
    cudaGetSymbolAddress(&p, g_w2);  __half* w2 = (__half*)p;

    cudaFuncSetAttribute(hmma_gemm<1>, cudaFuncAttributeMaxDynamicSharedMemorySize, GSMEM);
    cudaFuncSetAttribute(hmma_gemm<2>, cudaFuncAttributeMaxDynamicSharedMemorySize, GSMEM);
    cudaFuncSetAttribute(hmma_gemm<3>, cudaFuncAttributeMaxDynamicSharedMemorySize, GSMEM);
    cudaFuncSetAttribute(attn_hmma, cudaFuncAttributeMaxDynamicSharedMemorySize, ASMEM);

    // all 4 weight transposes in ONE launch (12288 tiles)
    wt_all_kernel<<<12288, dim3(32, 8)>>>(w_attn, wq, w_proj, wp, w_fc, wf, w_fc2, w2);

    // 1) ln1(x) -> fp16 (block per row)
    ln_h_kernel<<<ROWS, 256>>>(x, ln1_g, ln1_b, ah);
    // 2) qkv = ln1 @ w_attn + b_attn -> fp16 (q-part pre-scaled into exp2 domain)
    hmma_gemm<3><<<dim3(C3 / TILE_N, ROWS / TILE_M), 256, GSMEM>>>(
        ah, wq, b_attn, nullptr, nullptr, qv, ROWS, C3, CEMB);
    // 3) attention -> fp16 y (heavy q-tiles first)
    attn_hmma<<<dim3(SEQ / AQT, BATCH * NHEAD), 256, ASMEM>>>(qv, yh);
    // 4) x2 = x + y @ w_proj + b_proj (f32)
    hmma_gemm<2><<<dim3(CEMB / TILE_N, ROWS / TILE_M), 256, GSMEM>>>(
        yh, wp, b_proj, x, x2, nullptr, ROWS, CEMB, CEMB);
    // 5) ln2(x2) -> fp16 (block per row)
    ln_h_kernel<<<ROWS, 256>>>(x2, ln2_g, ln2_b, ah);
    // 6) h = gelu(ln2 @ w_fc + b_fc) -> fp16
    hmma_gemm<1><<<dim3(C4 / TILE_N, ROWS / TILE_M), 256, GSMEM>>>(
        ah, wf, b_fc, nullptr, nullptr, hh, ROWS, C4, CEMB);
    // 7) out = x2 + h @ w_fc2 + b_fc2 (f32)
    hmma_gemm<2><<<dim3(CEMB / TILE_N, ROWS / TILE_M), 256, GSMEM>>>(
        hh, w2, b_fc2, x2, out, nullptr, ROWS, CEMB, C4);
}